// round 3
// baseline (speedup 1.0000x reference)
#include <cuda_runtime.h>
#include <math.h>

#define HIDDEN   1024
#define NROW_MAX 8192
#define TILE     32
#define HSTRIDE  1025   // odd -> conflict-free rows
#define XSTRIDE  321

// scratch (static device arrays; no allocation)
__device__ int   g_code [NROW_MAX * 32];
__device__ float g_score[NROW_MAX * 32];

template<int H>
__device__ __forceinline__ void fwht_stage(float* v) {
#pragma unroll
    for (int q = 0; q < 32; q += 2 * H) {
#pragma unroll
        for (int p = 0; p < H; ++p) {
            float a = v[q + p], b = v[q + H + p];
            v[q + p]     = a + b;
            v[q + H + p] = a - b;
        }
    }
}

__device__ __forceinline__ void fwht32(float* v) {
    fwht_stage<1>(v);
    fwht_stage<2>(v);
    fwht_stage<4>(v);
    fwht_stage<8>(v);
    fwht_stage<16>(v);
}

// ---------------------------------------------------------------------------
// Phase 1: LayerNorm + BH4 (4 x [block-diag matmul + FWHT1024]) + code/score
// CTA: 32 rows, 512 threads (16 warps). lane = row within tile.
// ---------------------------------------------------------------------------
extern __shared__ float smem[];

__global__ __launch_bounds__(512, 1)
void phase1_kernel(const float* __restrict__ x,
                   const float* __restrict__ gamma,
                   const float* __restrict__ beta,
                   const float* __restrict__ W,     // [4][32][32][32]
                   const float* __restrict__ bias)  // [320]
{
    float* sH    = smem;                       // 32 * 1025
    float* sW    = sH + 32 * HSTRIDE;          // 8 * 1024  (8 blocks staged)
    float* sX    = sW + 8 * 1024;              // 32 * 321  (xn[:,:320] copy)
    float* sG    = sX + 32 * XSTRIDE;          // 1024
    float* sB    = sG + 1024;                  // 1024
    float* sBias = sB + 1024;                  // 320

    const int tid  = threadIdx.x;
    const int w    = tid >> 5;
    const int lane = tid & 31;
    const int row0 = blockIdx.x * TILE;

    for (int i = tid; i < 1024; i += 512) { sG[i] = gamma[i]; sB[i] = beta[i]; }
    for (int i = tid; i < 320;  i += 512) sBias[i] = bias[i];
    __syncthreads();

    // ---------------- LayerNorm: each warp handles 2 rows ----------------
#pragma unroll
    for (int it = 0; it < 2; ++it) {
        const int r = w * 2 + it;
        const float4* xr = (const float4*)(x + (size_t)(row0 + r) * HIDDEN);
        float4 v[8];
        float s = 0.f, ss = 0.f;
#pragma unroll
        for (int c = 0; c < 8; ++c) {
            v[c] = xr[c * 32 + lane];
            s  += v[c].x + v[c].y + v[c].z + v[c].w;
            ss += v[c].x * v[c].x + v[c].y * v[c].y + v[c].z * v[c].z + v[c].w * v[c].w;
        }
#pragma unroll
        for (int o = 16; o; o >>= 1) {
            s  += __shfl_xor_sync(0xffffffffu, s,  o);
            ss += __shfl_xor_sync(0xffffffffu, ss, o);
        }
        const float mu  = s * (1.f / 1024.f);
        const float var = ss * (1.f / 1024.f) - mu * mu;
        const float rs  = rsqrtf(var + 1e-12f);
        float* hr  = sH + r * HSTRIDE;
        float* xnr = sX + r * XSTRIDE;
#pragma unroll
        for (int c = 0; c < 8; ++c) {
            const int k = c * 128 + lane * 4;
            float xn0 = (v[c].x - mu) * rs * sG[k + 0] + sB[k + 0];
            float xn1 = (v[c].y - mu) * rs * sG[k + 1] + sB[k + 1];
            float xn2 = (v[c].z - mu) * rs * sG[k + 2] + sB[k + 2];
            float xn3 = (v[c].w - mu) * rs * sG[k + 3] + sB[k + 3];
            hr[k + 0] = xn0; hr[k + 1] = xn1; hr[k + 2] = xn2; hr[k + 3] = xn3;
            if (k < 320) {  // 320 % 4 == 0, whole quad in-range
                xnr[k + 0] = xn0; xnr[k + 1] = xn1;
                xnr[k + 2] = xn2; xnr[k + 3] = xn3;
            }
        }
    }
    __syncthreads();

    // ---------------- 4 BH4 stages ----------------
    const int bl = w >> 1;            // local block 0..7
    const int jb = (w & 1) * 16;      // j half

    for (int s = 0; s < 4; ++s) {
        // block-diagonal matmul, 8 blocks staged at a time
        for (int q = 0; q < 4; ++q) {
            __syncthreads();
            {   // stage 8 blocks (32 KB) of W into SMEM, coalesced
                const float4* wg  = (const float4*)(W + ((size_t)s * 32 + q * 8) * 1024);
                float4*       wsm = (float4*)sW;
                for (int i = tid; i < 2048; i += 512) wsm[i] = wg[i];
            }
            __syncthreads();

            float* hr = sH + lane * HSTRIDE + (q * 8 + bl) * 32;
            float hv[32];
#pragma unroll
            for (int i = 0; i < 32; ++i) hv[i] = hr[i];
            __syncthreads();   // all inputs of this quarter read before any write

            float acc[16];
#pragma unroll
            for (int jj = 0; jj < 16; ++jj) acc[jj] = 0.f;
            const float* wrow = sW + bl * 1024 + jb;
#pragma unroll
            for (int i = 0; i < 32; ++i) {
                const float h = hv[i];
                const float* wr = wrow + i * 32;   // warp-uniform -> LDS broadcast
#pragma unroll
                for (int jj = 0; jj < 16; ++jj) acc[jj] += h * wr[jj];
            }
#pragma unroll
            for (int jj = 0; jj < 16; ++jj) hr[jb + jj] = acc[jj];
        }
        __syncthreads();

        // FWHT1024 = (H32 x H32): pass A within 32-blocks
#pragma unroll
        for (int g = 0; g < 2; ++g) {
            float* p = sH + lane * HSTRIDE + (w + g * 16) * 32;
            float vv[32];
#pragma unroll
            for (int d = 0; d < 32; ++d) vv[d] = p[d];
            fwht32(vv);
#pragma unroll
            for (int d = 0; d < 32; ++d) p[d] = vv[d];
        }
        __syncthreads();

        // pass B across blocks (stride 32)
#pragma unroll
        for (int g = 0; g < 2; ++g) {
            float* p = sH + lane * HSTRIDE + (w + g * 16);
            float vv[32];
#pragma unroll
            for (int c = 0; c < 32; ++c) vv[c] = p[c * 32];
            fwht32(vv);
#pragma unroll
            for (int c = 0; c < 32; ++c) p[c * 32] = vv[c];
        }
        __syncthreads();
    }

    // ---------------- z -> code, score ----------------
#pragma unroll
    for (int tt = 0; tt < 2; ++tt) {
        const int t = w * 2 + tt;
        int code = 0;
        float sc = 1.f;
#pragma unroll
        for (int j = 0; j < 10; ++j) {
            const int k = t * 10 + j;
            const float z = 0.7f * sH[lane * HSTRIDE + k]
                          + 0.3f * sX[lane * XSTRIDE + k]
                          + sBias[k];
            if (z > 0.f) code |= (1 << j);
            sc *= 1.f / (1.f + expf(-fabsf(z)));
        }
        const int n = row0 + lane;
        g_code [n * 32 + t] = t * 1024 + code;   // pre-offset into flat table
        g_score[n * 32 + t] = sc;
    }
}

// ---------------------------------------------------------------------------
// Phase 2: out[n] = sum_t score[n,t] * tables_flat[code[n,t]] + out_bias
// One CTA per row; 256 threads x float4 = 1024 outputs. L2-bandwidth bound.
// ---------------------------------------------------------------------------
__global__ __launch_bounds__(256, 8)
void phase2_kernel(const float* __restrict__ tables,
                   const float* __restrict__ obias,
                   float* __restrict__ out)
{
    __shared__ float sc[32];
    __shared__ int   cd[32];
    const int n   = blockIdx.x;
    const int tid = threadIdx.x;
    if (tid < 32) {
        sc[tid] = g_score[n * 32 + tid];
        cd[tid] = g_code [n * 32 + tid];
    }
    __syncthreads();

    const float4* tb = (const float4*)tables;
    float4 a = ((const float4*)obias)[tid];
#pragma unroll 8
    for (int t = 0; t < 32; ++t) {
        const float4 v = __ldg(&tb[(size_t)cd[t] * 256 + tid]);
        const float  s = sc[t];
        a.x += s * v.x; a.y += s * v.y; a.z += s * v.z; a.w += s * v.w;
    }
    ((float4*)out)[(size_t)n * 256 + tid] = a;
}

// ---------------------------------------------------------------------------
extern "C" void kernel_launch(void* const* d_in, const int* in_sizes, int n_in,
                              void* d_out, int out_size)
{
    const float* x      = (const float*)d_in[0];   // hidden_states
    const float* gamma  = (const float*)d_in[1];
    const float* beta   = (const float*)d_in[2];
    const float* W      = (const float*)d_in[3];   // bh4_weight
    const float* bias   = (const float*)d_in[4];   // bh4_bias
    const float* tables = (const float*)d_in[5];
    const float* obias  = (const float*)d_in[6];
    float* out = (float*)d_out;

    const int nrows = in_sizes[0] / HIDDEN;        // 8192

    const size_t smem_bytes =
        (size_t)(32 * HSTRIDE + 8 * 1024 + 32 * XSTRIDE + 1024 + 1024 + 320) * sizeof(float);
    cudaFuncSetAttribute(phase1_kernel,
                         cudaFuncAttributeMaxDynamicSharedMemorySize,
                         (int)smem_bytes);

    phase1_kernel<<<nrows / TILE, 512, smem_bytes>>>(x, gamma, beta, W, bias);
    phase2_kernel<<<nrows, 256>>>(tables, obias, out);
}

// round 4
// speedup vs baseline: 1.1012x; 1.1012x over previous
#include <cuda_runtime.h>
#include <math.h>

#define HIDDEN   1024
#define NROW_MAX 8192
#define TILE     16
#define HSTRIDE  1026    // even, ==2 mod 32: conflict-free pass-B, 8B-aligned rows

// scratch (static device arrays; no allocation)
__device__ int   g_code [NROW_MAX * 32];
__device__ float g_score[NROW_MAX * 32];

typedef unsigned long long ull;

__device__ __forceinline__ ull pack2(float lo, float hi) {
    ull r; asm("mov.b64 %0, {%1, %2};" : "=l"(r) : "f"(lo), "f"(hi)); return r;
}
__device__ __forceinline__ void fma2(ull& d, ull a, ull b, ull c) {
    asm("fma.rn.f32x2 %0, %1, %2, %3;" : "=l"(d) : "l"(a), "l"(b), "l"(c));
}
__device__ __forceinline__ void unpack2(ull v, float& lo, float& hi) {
    asm("mov.b64 {%0, %1}, %2;" : "=f"(lo), "=f"(hi) : "l"(v));
}

template<int N, int H>
__device__ __forceinline__ void fwht_stage(float* v) {
#pragma unroll
    for (int q = 0; q < N; q += 2 * H)
#pragma unroll
        for (int p = 0; p < H; ++p) {
            float a = v[q + p], b = v[q + H + p];
            v[q + p] = a + b; v[q + H + p] = a - b;
        }
}
__device__ __forceinline__ void fwht16(float* v) {
    fwht_stage<16,1>(v); fwht_stage<16,2>(v); fwht_stage<16,4>(v); fwht_stage<16,8>(v);
}
__device__ __forceinline__ void fwht32(float* v) {
    fwht_stage<32,1>(v); fwht_stage<32,2>(v); fwht_stage<32,4>(v);
    fwht_stage<32,8>(v); fwht_stage<32,16>(v);
}

// ---------------------------------------------------------------------------
// Phase 1: LN + BH4 (4 stages) + code/score.
// CTA: 16 rows, 256 threads (8 warps), 2 CTAs/SM.
// Matmul mapping: warp w = staged block, lane: row = lane&15, jq = lane>>4.
// FWHT pass A fused into matmul epilogue (fwht16 + shfl butterfly).
// ---------------------------------------------------------------------------
extern __shared__ float smem[];

__global__ __launch_bounds__(256, 2)
void phase1_kernel(const float* __restrict__ x,
                   const float* __restrict__ gamma,
                   const float* __restrict__ beta,
                   const float* __restrict__ W,     // [4][32][32][32]
                   const float* __restrict__ bias)  // [320]
{
    float* sH  = smem;                     // 16 * 1026
    float* sW  = sH + TILE * HSTRIDE;      // 8 * 1024
    float* sMu = sW + 8 * 1024;            // 16
    float* sRs = sMu + 16;                 // 16

    const int tid  = threadIdx.x;
    const int w    = tid >> 5;
    const int lane = tid & 31;
    const int row0 = blockIdx.x * TILE;

    // ---------------- LayerNorm: each warp handles 2 rows ----------------
#pragma unroll
    for (int it = 0; it < 2; ++it) {
        const int r = w * 2 + it;
        const float4* xr = (const float4*)(x + (size_t)(row0 + r) * HIDDEN);
        float4 v[8];
        float s = 0.f, ss = 0.f;
#pragma unroll
        for (int c = 0; c < 8; ++c) {
            v[c] = xr[c * 32 + lane];
            s  += v[c].x + v[c].y + v[c].z + v[c].w;
            ss += v[c].x * v[c].x + v[c].y * v[c].y + v[c].z * v[c].z + v[c].w * v[c].w;
        }
#pragma unroll
        for (int o = 16; o; o >>= 1) {
            s  += __shfl_xor_sync(0xffffffffu, s,  o);
            ss += __shfl_xor_sync(0xffffffffu, ss, o);
        }
        const float mu  = s * (1.f / 1024.f);
        const float var = ss * (1.f / 1024.f) - mu * mu;
        const float rs  = rsqrtf(var + 1e-12f);
        if (lane == 0) { sMu[r] = mu; sRs[r] = rs; }
        float* hr = sH + r * HSTRIDE;
#pragma unroll
        for (int c = 0; c < 8; ++c) {
            const int k = c * 128 + lane * 4;
            const float4 gm = ((const float4*)gamma)[c * 32 + lane];
            const float4 bt = ((const float4*)beta )[c * 32 + lane];
            hr[k + 0] = (v[c].x - mu) * rs * gm.x + bt.x;
            hr[k + 1] = (v[c].y - mu) * rs * gm.y + bt.y;
            hr[k + 2] = (v[c].z - mu) * rs * gm.z + bt.z;
            hr[k + 3] = (v[c].w - mu) * rs * gm.w + bt.w;
        }
    }

    const int row = lane & 15;
    const int jq  = lane >> 4;

    // ---------------- 4 BH4 stages ----------------
    for (int s = 0; s < 4; ++s) {
        for (int q = 0; q < 4; ++q) {
            __syncthreads();   // prior readers of sW (and stage-entry hazards) done
            {   // stage 8 blocks (32 KB) of W, coalesced
                const float4* wg = (const float4*)(W + ((size_t)s * 32 + q * 8) * 1024);
                float4*       wd = (float4*)sW;
#pragma unroll
                for (int i = 0; i < 8; ++i) wd[tid + i * 256] = wg[tid + i * 256];
            }
            __syncthreads();

            const int blk = q * 8 + w;
            float* hrow = sH + row * HSTRIDE + blk * 32;

            float hv[32];
#pragma unroll
            for (int i = 0; i < 32; ++i) hv[i] = hrow[i];   // 2-lane broadcast

            ull acc2[8];
#pragma unroll
            for (int k = 0; k < 8; ++k) acc2[k] = 0ull;

            const float* wbase = sW + w * 1024 + jq * 16;
#pragma unroll
            for (int i = 0; i < 32; ++i) {
                const ull hh = pack2(hv[i], hv[i]);
                const ulonglong2* wv = (const ulonglong2*)(wbase + i * 32);
                ulonglong2 wa = wv[0], wb = wv[1];
                fma2(acc2[0], hh, wa.x, acc2[0]); fma2(acc2[1], hh, wa.y, acc2[1]);
                fma2(acc2[2], hh, wb.x, acc2[2]); fma2(acc2[3], hh, wb.y, acc2[3]);
                wa = wv[2]; wb = wv[3];
                fma2(acc2[4], hh, wa.x, acc2[4]); fma2(acc2[5], hh, wa.y, acc2[5]);
                fma2(acc2[6], hh, wb.x, acc2[6]); fma2(acc2[7], hh, wb.y, acc2[7]);
            }

            // fused FWHT pass A: fwht16 on this half, then cross-half butterfly
            float va[16];
#pragma unroll
            for (int k = 0; k < 8; ++k) unpack2(acc2[k], va[2 * k], va[2 * k + 1]);
            fwht16(va);
#pragma unroll
            for (int k = 0; k < 16; ++k) {
                const float o = __shfl_xor_sync(0xffffffffu, va[k], 16);
                va[k] = (jq == 0) ? (va[k] + o) : (o - va[k]);
            }
#pragma unroll
            for (int k = 0; k < 16; ++k) hrow[jq * 16 + k] = va[k];
        }
        __syncthreads();

        // FWHT pass B: across 32-blocks (stride 32), conflict-free w/ HSTRIDE=1026
#pragma unroll
        for (int g = 0; g < 2; ++g) {
            const int id = tid + g * 256;
            float* p = sH + (id & 15) * HSTRIDE + (id >> 4);
            float vv[32];
#pragma unroll
            for (int c = 0; c < 32; ++c) vv[c] = p[c * 32];
            fwht32(vv);
#pragma unroll
            for (int c = 0; c < 32; ++c) p[c * 32] = vv[c];
        }
        // next stage begins with __syncthreads() at q=0
    }
    __syncthreads();

    // ---------------- z -> code, score (xn recomputed from x, mu, rs) -------
#pragma unroll
    for (int g = 0; g < 2; ++g) {
        const int id = tid + g * 256;
        const int r  = id & 15;
        const int t  = id >> 4;
        const int n  = row0 + r;
        const float mu = sMu[r], rs = sRs[r];
        const float* xrow = x + (size_t)n * HIDDEN;
        int code = 0;
        float sc = 1.f;
#pragma unroll
        for (int j = 0; j < 10; ++j) {
            const int k = t * 10 + j;
            const float xn = (xrow[k] - mu) * rs * gamma[k] + beta[k];
            const float z  = 0.7f * sH[r * HSTRIDE + k] + 0.3f * xn + bias[k];
            if (z > 0.f) code |= (1 << j);
            sc *= 1.f / (1.f + expf(-fabsf(z)));
        }
        g_code [n * 32 + t] = t * 1024 + code;   // pre-offset into flat table
        g_score[n * 32 + t] = sc;
    }
}

// ---------------------------------------------------------------------------
// Phase 2: out[n] = sum_t score[n,t] * tables_flat[code[n,t]] + out_bias
// 16 rows per CTA, register accumulators, table loop OUTERMOST so all
// concurrent CTAs touch the same table segment -> L2-resident working set.
// ---------------------------------------------------------------------------
__global__ __launch_bounds__(256, 2)
void phase2_kernel(const float* __restrict__ tables,
                   const float* __restrict__ obias,
                   float* __restrict__ out)
{
    __shared__ float sc[32][16];
    __shared__ int   cd[32][16];
    const int n0  = blockIdx.x * 16;
    const int tid = threadIdx.x;

#pragma unroll
    for (int g = 0; g < 2; ++g) {
        const int id = tid + g * 256;
        const int r  = id & 15;
        const int t  = id >> 4;
        sc[t][r] = g_score[(n0 + r) * 32 + t];
        cd[t][r] = g_code [(n0 + r) * 32 + t];
    }
    __syncthreads();

    const float4 ob = ((const float4*)obias)[tid];
    float4 a[16];
#pragma unroll
    for (int r = 0; r < 16; ++r) a[r] = ob;

    const float4* tb = (const float4*)tables;
#pragma unroll 1
    for (int t = 0; t < 32; ++t) {
#pragma unroll
        for (int r = 0; r < 16; ++r) {
            const float4 v = __ldg(&tb[(size_t)cd[t][r] * 256 + tid]);
            const float  s = sc[t][r];
            a[r].x += s * v.x; a[r].y += s * v.y;
            a[r].z += s * v.z; a[r].w += s * v.w;
        }
    }

#pragma unroll
    for (int r = 0; r < 16; ++r)
        ((float4*)out)[(size_t)(n0 + r) * 256 + tid] = a[r];
}

// ---------------------------------------------------------------------------
extern "C" void kernel_launch(void* const* d_in, const int* in_sizes, int n_in,
                              void* d_out, int out_size)
{
    const float* x      = (const float*)d_in[0];   // hidden_states
    const float* gamma  = (const float*)d_in[1];
    const float* beta   = (const float*)d_in[2];
    const float* W      = (const float*)d_in[3];   // bh4_weight
    const float* bias   = (const float*)d_in[4];   // bh4_bias
    const float* tables = (const float*)d_in[5];
    const float* obias  = (const float*)d_in[6];
    float* out = (float*)d_out;

    const int nrows = in_sizes[0] / HIDDEN;        // 8192

    const size_t smem_bytes =
        (size_t)(TILE * HSTRIDE + 8 * 1024 + 32) * sizeof(float);   // ~98.6 KB
    cudaFuncSetAttribute(phase1_kernel,
                         cudaFuncAttributeMaxDynamicSharedMemorySize,
                         (int)smem_bytes);

    phase1_kernel<<<nrows / TILE, 256, smem_bytes>>>(x, gamma, beta, W, bias);
    phase2_kernel<<<nrows / 16, 256>>>(tables, obias, out);
}